// round 13
// baseline (speedup 1.0000x reference)
#include <cuda_runtime.h>
#include <math.h>
#include <stdint.h>

// ---------------- problem constants ----------------
#define BB 2
#define SS 2048
#define EE 1024
#define HH 16
#define HD 64
#define ROWS (BB*SS)           // 4096
#define NHROWS (BB*HH*SS)      // 65536
#define PROJ_ELEMS (ROWS*EE)   // 4194304
#define ATTN_ELEMS (BB*HH*SS*SS) // 134217728

// ---------------- scratch ----------------
__device__ float g_proj[3][PROJ_ELEMS];
__device__ float4 g_qsp[NHROWS * 32];   // Q split, fragment layout (32MB)
__device__ float4 g_ksp[NHROWS * 32];   // K split, fragment layout (32MB)
__device__ float g_vh[PROJ_ELEMS];      // V heads, tf32-hi values (16MB)
__device__ float g_zc[PROJ_ELEMS];
__device__ float g_m[NHROWS];
__device__ float g_l[NHROWS];

// ---------------- tf32 helpers ----------------
__device__ __forceinline__ float2 tf32split(float x) {
    uint32_t hi;
    asm("cvt.rna.tf32.f32 %0, %1;" : "=r"(hi) : "f"(x));
    float h = __uint_as_float(hi);
    uint32_t lo;
    asm("cvt.rna.tf32.f32 %0, %1;" : "=r"(lo) : "f"(x - h));
    return make_float2(h, __uint_as_float(lo));
}

__device__ __forceinline__ float tf32hi(float x) {
    uint32_t hi;
    asm("cvt.rna.tf32.f32 %0, %1;" : "=r"(hi) : "f"(x));
    return __uint_as_float(hi);
}

__device__ __forceinline__ void mma8(float c[4],
                                     uint32_t a0, uint32_t a1, uint32_t a2, uint32_t a3,
                                     uint32_t b0, uint32_t b1) {
    asm volatile(
        "mma.sync.aligned.m16n8k8.row.col.f32.tf32.tf32.f32 "
        "{%0,%1,%2,%3}, {%4,%5,%6,%7}, {%8,%9}, {%0,%1,%2,%3};\n"
        : "+f"(c[0]), "+f"(c[1]), "+f"(c[2]), "+f"(c[3])
        : "r"(a0), "r"(a1), "r"(a2), "r"(a3), "r"(b0), "r"(b1));
}

#define F2U(x) __float_as_uint(x)

// 3xTF32 (hi*hi + hi*lo + lo*hi), fp32 accumulate. f = {hi_a, lo_a, hi_b, lo_b}
__device__ __forceinline__ void mma3x4(float c[4],
                                       const float4 f0, const float4 f1,
                                       const float4 bf) {
    mma8(c, F2U(f0.x), F2U(f1.x), F2U(f0.z), F2U(f1.z), F2U(bf.x), F2U(bf.z));
    mma8(c, F2U(f0.x), F2U(f1.x), F2U(f0.z), F2U(f1.z), F2U(bf.y), F2U(bf.w));
    mma8(c, F2U(f0.y), F2U(f1.y), F2U(f0.w), F2U(f1.w), F2U(bf.x), F2U(bf.z));
}

// 1xTF32 on float2 hi-only fragments: f = {hi(k=t), hi(k=t+4)}
__device__ __forceinline__ void mma1x2(float c[4],
                                       const float2 f0, const float2 f1,
                                       const float2 bf) {
    mma8(c, F2U(f0.x), F2U(f1.x), F2U(f0.y), F2U(f1.y), F2U(bf.x), F2U(bf.y));
}

__device__ __forceinline__ float4 packsplit(float v0, float v1) {
    float2 h0 = tf32split(v0);
    float2 h1 = tf32split(v1);
    return make_float4(h0.x, h0.y, h1.x, h1.y);
}

// =============================================================================
// Batched 128x128x16 3xTF32 GEMM (q,k projections), double-buffered (R8 config).
// =============================================================================
struct GemmBatch {
    const float* A[2];
    const float* B[2];
    const float* bias[2];
    float* C[2];
};

#define BUFSZ  (2*4*130)

__global__ __launch_bounds__(256) void gemm_3x(GemmBatch args, int M, int N, int K)
{
    extern __shared__ float4 smemg[];
    float4 (*Apk)[2][4][130] = (float4(*)[2][4][130])smemg;
    float4 (*Bpk)[2][4][130] = (float4(*)[2][4][130])(smemg + 2 * BUFSZ);

    const float* A    = args.A[blockIdx.z];
    const float* B    = args.B[blockIdx.z];
    const float* bias = args.bias[blockIdx.z];
    float*       C    = args.C[blockIdx.z];

    int tid = threadIdx.x;
    int wid = tid >> 5, lane = tid & 31;
    int g = lane >> 2, t = lane & 3;
    int wm = wid >> 2, wn = wid & 3;
    int m0 = blockIdx.y * 128, n0 = blockIdx.x * 128;

    int ma = tid & 127, ha = tid >> 7;
    int nq = tid & 31,  kr = tid >> 5;
    int bs = kr >> 2,   bt = kr & 3;

    float acc[4][4][4];
#pragma unroll
    for (int mt = 0; mt < 4; mt++)
#pragma unroll
        for (int nt = 0; nt < 4; nt++)
#pragma unroll
            for (int c = 0; c < 4; c++) acc[mt][nt][c] = 0.f;

    const int NC = K / 16;
    float4 pa0, pa1, pb0, pb1;
    {
        const float* pA = A + (size_t)(m0 + ma) * K + ha * 8;
        pa0 = *(const float4*)pA;
        pa1 = *(const float4*)(pA + 4);
        const float* pB = B + (size_t)(bs * 8 + bt) * N + n0 + nq * 4;
        pb0 = *(const float4*)pB;
        pb1 = *(const float4*)(pB + 4 * (size_t)N);
    }

    for (int c = 0; c < NC; c++) {
        int buf = c & 1;
        {
            float va[8] = {pa0.x, pa0.y, pa0.z, pa0.w, pa1.x, pa1.y, pa1.z, pa1.w};
            float vb0[4] = {pb0.x, pb0.y, pb0.z, pb0.w};
            float vb1[4] = {pb1.x, pb1.y, pb1.z, pb1.w};
#pragma unroll
            for (int tt = 0; tt < 4; tt++)
                Apk[buf][ha][tt][ma] = packsplit(va[tt], va[tt + 4]);
#pragma unroll
            for (int j = 0; j < 4; j++)
                Bpk[buf][bs][bt][nq * 4 + j] = packsplit(vb0[j], vb1[j]);
        }
        if (c + 1 < NC) {
            int k0 = (c + 1) * 16;
            const float* pA = A + (size_t)(m0 + ma) * K + k0 + ha * 8;
            pa0 = *(const float4*)pA;
            pa1 = *(const float4*)(pA + 4);
            const float* pB = B + (size_t)(k0 + bs * 8 + bt) * N + n0 + nq * 4;
            pb0 = *(const float4*)pB;
            pb1 = *(const float4*)(pB + 4 * (size_t)N);
        }
        __syncthreads();
#pragma unroll
        for (int s = 0; s < 2; s++) {
            float4 af0[4], af1[4];
#pragma unroll
            for (int mt = 0; mt < 4; mt++) {
                int rb = wm * 64 + mt * 16;
                af0[mt] = Apk[buf][s][t][rb + g];
                af1[mt] = Apk[buf][s][t][rb + g + 8];
            }
#pragma unroll
            for (int nt = 0; nt < 4; nt++) {
                float4 bf = Bpk[buf][s][t][wn * 32 + nt * 8 + g];
#pragma unroll
                for (int mt = 0; mt < 4; mt++)
                    mma3x4(acc[mt][nt], af0[mt], af1[mt], bf);
            }
        }
    }

#pragma unroll
    for (int mt = 0; mt < 4; mt++) {
        int r = m0 + wm * 64 + mt * 16 + g;
#pragma unroll
        for (int nt = 0; nt < 4; nt++) {
            int cc = n0 + wn * 32 + nt * 8 + 2 * t;
            float bb0 = bias[cc], bb1 = bias[cc + 1];
            *(float2*)&C[(size_t)r * N + cc] =
                make_float2(acc[mt][nt][0] + bb0, acc[mt][nt][1] + bb1);
            *(float2*)&C[(size_t)(r + 8) * N + cc] =
                make_float2(acc[mt][nt][2] + bb0, acc[mt][nt][3] + bb1);
        }
    }
}

// =============================================================================
// 128x128x16 1xTF32 GEMM, float2 hi-only smem, 2 CTAs/SM.
// =============================================================================
__global__ __launch_bounds__(256, 2) void gemm_1x(const float* __restrict__ A,
                                                  const float* __restrict__ B,
                                                  const float* __restrict__ bias,
                                                  float* __restrict__ C,
                                                  int M, int N, int K)
{
    __shared__ float2 A2[2][2][4][132];
    __shared__ float2 B2[2][2][4][132];

    int tid = threadIdx.x;
    int wid = tid >> 5, lane = tid & 31;
    int g = lane >> 2, t = lane & 3;
    int wm = wid >> 2, wn = wid & 3;
    int m0 = blockIdx.y * 128, n0 = blockIdx.x * 128;

    int ma = tid & 127, ha = tid >> 7;
    int nq = tid & 31,  kr = tid >> 5;
    int bs = kr >> 2,   bt = kr & 3;

    float acc[4][4][4];
#pragma unroll
    for (int mt = 0; mt < 4; mt++)
#pragma unroll
        for (int nt = 0; nt < 4; nt++)
#pragma unroll
            for (int c = 0; c < 4; c++) acc[mt][nt][c] = 0.f;

    const int NC = K / 16;
    float4 pa0, pa1;
    float vb0[4], vb1[4];
    {
        const float* pA = A + (size_t)(m0 + ma) * K + ha * 8;
        pa0 = *(const float4*)pA;
        pa1 = *(const float4*)(pA + 4);
        const float* pB0 = B + (size_t)(bs * 8 + bt) * N + n0 + nq;
        const float* pB1 = pB0 + 4 * (size_t)N;
#pragma unroll
        for (int j = 0; j < 4; j++) { vb0[j] = pB0[j * 32]; vb1[j] = pB1[j * 32]; }
    }

    for (int c = 0; c < NC; c++) {
        int buf = c & 1;
        {
            float va[8] = {pa0.x, pa0.y, pa0.z, pa0.w, pa1.x, pa1.y, pa1.z, pa1.w};
#pragma unroll
            for (int tt = 0; tt < 4; tt++)
                A2[buf][ha][tt][ma] = make_float2(tf32hi(va[tt]), tf32hi(va[tt + 4]));
#pragma unroll
            for (int j = 0; j < 4; j++)
                B2[buf][bs][bt][j * 32 + nq] = make_float2(tf32hi(vb0[j]), tf32hi(vb1[j]));
        }
        if (c + 1 < NC) {
            int k0 = (c + 1) * 16;
            const float* pA = A + (size_t)(m0 + ma) * K + k0 + ha * 8;
            pa0 = *(const float4*)pA;
            pa1 = *(const float4*)(pA + 4);
            const float* pB0 = B + (size_t)(k0 + bs * 8 + bt) * N + n0 + nq;
            const float* pB1 = pB0 + 4 * (size_t)N;
#pragma unroll
            for (int j = 0; j < 4; j++) { vb0[j] = pB0[j * 32]; vb1[j] = pB1[j * 32]; }
        }
        __syncthreads();
#pragma unroll
        for (int s = 0; s < 2; s++) {
            float2 af0[4], af1[4];
#pragma unroll
            for (int mt = 0; mt < 4; mt++) {
                int rb = wm * 64 + mt * 16;
                af0[mt] = A2[buf][s][t][rb + g];
                af1[mt] = A2[buf][s][t][rb + g + 8];
            }
#pragma unroll
            for (int nt = 0; nt < 4; nt++) {
                float2 bf = B2[buf][s][t][wn * 32 + nt * 8 + g];
#pragma unroll
                for (int mt = 0; mt < 4; mt++)
                    mma1x2(acc[mt][nt], af0[mt], af1[mt], bf);
            }
        }
    }

#pragma unroll
    for (int mt = 0; mt < 4; mt++) {
        int r = m0 + wm * 64 + mt * 16 + g;
#pragma unroll
        for (int nt = 0; nt < 4; nt++) {
            int cc = n0 + wn * 32 + nt * 8 + 2 * t;
            float bb0 = bias[cc], bb1 = bias[cc + 1];
            *(float2*)&C[(size_t)r * N + cc] =
                make_float2(acc[mt][nt][0] + bb0, acc[mt][nt][1] + bb1);
            *(float2*)&C[(size_t)(r + 8) * N + cc] =
                make_float2(acc[mt][nt][2] + bb0, acc[mt][nt][3] + bb1);
        }
    }
}

// =============================================================================
// Fused gather + normalize + tf32 pre-split.
// which 0/1 (q,k): writes fragment-layout float4 {hi(d0),lo(d0),hi(d0+4),lo(d0+4)}
//   at index j: d0 = 8*(j>>2)+(j&3).
// which 2 (v): writes tf32-hi values in row-major head layout.
// =============================================================================
__global__ __launch_bounds__(256) void gather_norm3(const float* __restrict__ proj_base,
                                                    float4* __restrict__ qsp,
                                                    float4* __restrict__ ksp,
                                                    float* __restrict__ vh)
{
    int which = blockIdx.y;
    const float* proj = proj_base + (size_t)which * PROJ_ELEMS;

    int w = blockIdx.x * 8 + (threadIdx.x >> 5);
    int lane = threadIdx.x & 31;
    int b2 = w >> 15;
    int h  = (w >> 11) & 15;
    int s2 = w & 2047;
    int e = b2 * 512 + h * 32 + (s2 >> 6);
    int s = ((s2 & 63) << 5) + lane;
    float v0 = proj[(size_t)s * EE + e];            // d = 2*lane
    float v1 = proj[(size_t)(SS + s) * EE + e];     // d = 2*lane + 1

    if (which == 2) {
        // V: tf32-hi values, row-major
        ((float2*)vh)[(size_t)w * 32 + lane] =
            make_float2(tf32hi(v0), tf32hi(v1));
        return;
    }

    // normalize
    float ssq = v0 * v0 + v1 * v1;
#pragma unroll
    for (int o = 16; o; o >>= 1) ssq += __shfl_xor_sync(0xffffffffu, ssq, o);
    float rn = rsqrtf(ssq);
    v0 *= rn;
    v1 *= rn;

    // fragment-layout split: lane computes fragment j = lane
    int j = lane;
    int d0 = ((j >> 2) << 3) + (j & 3);
    int src0 = d0 >> 1;         // lane holding d0 (slot d0&1)
    int src1 = src0 + 2;        // lane holding d0+4 (same parity)
    float a0 = __shfl_sync(0xffffffffu, v0, src0);
    float b0 = __shfl_sync(0xffffffffu, v1, src0);
    float a1 = __shfl_sync(0xffffffffu, v0, src1);
    float b1 = __shfl_sync(0xffffffffu, v1, src1);
    float xa = (d0 & 1) ? b0 : a0;
    float xb = (d0 & 1) ? b1 : a1;
    float4* outp = which ? ksp : qsp;
    outp[(size_t)w * 32 + j] = packsplit(xa, xb);
}

// =============================================================================
// mma flash attention, BQ=64 / BK=32, 128 threads, 3 CTAs/SM, LPT ordering.
// Q/K staged from pre-split fragment arrays (pure copy, no cvt);
// V staged from pre-converted hi values (pack only). Streams raw logits.
// =============================================================================
#define Q_SZ4 (8*4*66)   // float4s
#define K_SZ4 (8*4*34)   // float4s
#define V_SZ2 (4*4*68)   // float2s
#define P_SZ2 (4*4*68)   // float2s

__global__ __launch_bounds__(128, 3) void attn_mma(const float4* __restrict__ qsp,
                                                   const float4* __restrict__ ksp,
                                                   const float* __restrict__ vh,
                                                   float* __restrict__ zc,
                                                   float* __restrict__ gm,
                                                   float* __restrict__ gl,
                                                   float* __restrict__ pattn)
{
    extern __shared__ float4 sm4[];
    float4 (*Qpk)[4][66] = (float4(*)[4][66])sm4;                      // [8][4][66] f4
    float4 (*Kpk)[4][34] = (float4(*)[4][34])(sm4 + Q_SZ4);            // [8][4][34] f4
    float2 (*V2)[4][68]  = (float2(*)[4][68])(sm4 + Q_SZ4 + K_SZ4);    // [4][4][68] f2
    float2 (*P2)[4][68]  = (float2(*)[4][68])((float2*)(sm4 + Q_SZ4 + K_SZ4) + V_SZ2);

    int tid = threadIdx.x;
    int w = tid >> 5, lane = tid & 31;
    int g = lane >> 2, t = lane & 3;
    int qb = (gridDim.x - 1) - blockIdx.x;   // LPT: heavy blocks first
    int h = blockIdx.y, b2 = blockIdx.z;
    int base = (b2 * HH + h) * SS;
    size_t obase = (size_t)(b2 * HH + h) * SS * SS;
    int q0 = qb * 64;
    int r0 = w * 16;

    // ---- stage Q: copy from pre-split fragment array ----
    {
        int m = tid >> 1, hs = tid & 1;
        const float4* src = qsp + (size_t)(base + q0 + m) * 32 + hs * 16;
#pragma unroll
        for (int i = 0; i < 16; i++) {
            int sp = i >> 2, tt = i & 3;
            Qpk[hs * 4 + sp][tt][m] = src[i];
        }
    }

    float oacc[8][4];
#pragma unroll
    for (int nt = 0; nt < 8; nt++)
#pragma unroll
        for (int c = 0; c < 4; c++) oacc[nt][c] = 0.f;
    float m0 = -1e30f, m1 = -1e30f, l0 = 0.f, l1 = 0.f;

    int row0 = q0 + r0 + g, row1 = row0 + 8;
    int nkb = 2 * (qb + 1);

    for (int kb = 0; kb < nkb; kb++) {
        int k0 = kb * 32;
        __syncthreads();
        // ---- stage K: copy from pre-split fragment array ----
        {
            int n = tid >> 2, qk = tid & 3;
            const float4* src = ksp + (size_t)(base + k0 + n) * 32 + qk * 8;
#pragma unroll
            for (int i = 0; i < 8; i++) {
                int sp = i >> 2, tt = i & 3;
                Kpk[qk * 2 + sp][tt][n] = src[i];
            }
        }
        // ---- stage V (values already tf32-hi; pack rows r, r+4) ----
        {
            int n4 = tid & 15;
            int comb = tid >> 4;
            int s = comb >> 1, tb = (comb & 1) * 2;
#pragma unroll
            for (int dt = 0; dt < 2; dt++) {
                int tt = tb + dt;
                const float* p = vh + (size_t)(base + k0 + 8 * s + tt) * HD + n4 * 4;
                float4 x0 = *(const float4*)p;
                float4 x1 = *(const float4*)(p + 4 * HD);
                const float* f0 = (const float*)&x0;
                const float* f1 = (const float*)&x1;
#pragma unroll
                for (int j = 0; j < 4; j++)
                    V2[s][tt][n4 * 4 + j] = make_float2(f0[j], f1[j]);
            }
        }
        __syncthreads();

        if (k0 > q0 + r0 + 15) continue;

        // ---- S = Q @ K^T (3xTF32) ----
        float sacc[4][4];
#pragma unroll
        for (int nt = 0; nt < 4; nt++)
#pragma unroll
            for (int c = 0; c < 4; c++) sacc[nt][c] = 0.f;
#pragma unroll
        for (int ks = 0; ks < 8; ks++) {
            float4 f0 = Qpk[ks][t][r0 + g];
            float4 f1 = Qpk[ks][t][r0 + g + 8];
#pragma unroll
            for (int nt = 0; nt < 4; nt++) {
                float4 bf = Kpk[ks][t][nt * 8 + g];
                mma3x4(sacc[nt], f0, f1, bf);
            }
        }

        // ---- scale + mask ----
        bool nm = (k0 + 31 > q0 + r0);
        float sv[4][4];
        float mx0 = -1e30f, mx1 = -1e30f;
#pragma unroll
        for (int nt = 0; nt < 4; nt++) {
            int cb = k0 + nt * 8 + 2 * t;
            float s0 = sacc[nt][0] * 1000.f;
            float s1 = sacc[nt][1] * 1000.f;
            float s2 = sacc[nt][2] * 1000.f;
            float s3 = sacc[nt][3] * 1000.f;
            if (nm) {
                if (cb > row0) s0 = -1e30f;
                if (cb + 1 > row0) s1 = -1e30f;
                if (cb > row1) s2 = -1e30f;
                if (cb + 1 > row1) s3 = -1e30f;
            }
            sv[nt][0] = s0; sv[nt][1] = s1; sv[nt][2] = s2; sv[nt][3] = s3;
            mx0 = fmaxf(mx0, fmaxf(s0, s1));
            mx1 = fmaxf(mx1, fmaxf(s2, s3));
        }

        // ---- stream logits to attn buffer ----
        if (pattn) {
#pragma unroll
            for (int nt = 0; nt < 4; nt++) {
                int jg = k0 + nt * 8 + 2 * t;
                *(float2*)&pattn[obase + (size_t)row0 * SS + jg] = make_float2(sv[nt][0], sv[nt][1]);
                *(float2*)&pattn[obase + (size_t)row1 * SS + jg] = make_float2(sv[nt][2], sv[nt][3]);
            }
        }

        // ---- online softmax ----
        mx0 = fmaxf(mx0, __shfl_xor_sync(0xffffffffu, mx0, 1));
        mx0 = fmaxf(mx0, __shfl_xor_sync(0xffffffffu, mx0, 2));
        mx1 = fmaxf(mx1, __shfl_xor_sync(0xffffffffu, mx1, 1));
        mx1 = fmaxf(mx1, __shfl_xor_sync(0xffffffffu, mx1, 2));
        float mn0 = fmaxf(m0, mx0), mn1 = fmaxf(m1, mx1);
        float sc0 = __expf(m0 - mn0), sc1 = __expf(m1 - mn1);
        m0 = mn0; m1 = mn1;
        float rs0 = 0.f, rs1 = 0.f;
        int tpA = (2 * t) & 3, tpB = (2 * t + 1) & 3;
        int slot = (t >= 2);
#pragma unroll
        for (int nt = 0; nt < 4; nt++) {
            float p0 = __expf(sv[nt][0] - mn0);
            float p1 = __expf(sv[nt][1] - mn0);
            float p2 = __expf(sv[nt][2] - mn1);
            float p3 = __expf(sv[nt][3] - mn1);
            rs0 += p0 + p1;
            rs1 += p2 + p3;
            ((float*)&P2[nt][tpA][r0 + g])[slot]     = tf32hi(p0);
            ((float*)&P2[nt][tpB][r0 + g])[slot]     = tf32hi(p1);
            ((float*)&P2[nt][tpA][r0 + g + 8])[slot] = tf32hi(p2);
            ((float*)&P2[nt][tpB][r0 + g + 8])[slot] = tf32hi(p3);
        }
        rs0 += __shfl_xor_sync(0xffffffffu, rs0, 1);
        rs0 += __shfl_xor_sync(0xffffffffu, rs0, 2);
        rs1 += __shfl_xor_sync(0xffffffffu, rs1, 1);
        rs1 += __shfl_xor_sync(0xffffffffu, rs1, 2);
        l0 = l0 * sc0 + rs0;
        l1 = l1 * sc1 + rs1;
#pragma unroll
        for (int nt = 0; nt < 8; nt++) {
            oacc[nt][0] *= sc0; oacc[nt][1] *= sc0;
            oacc[nt][2] *= sc1; oacc[nt][3] *= sc1;
        }
        __syncwarp();

        // ---- O += P @ V (1xTF32, float2 fragments) ----
#pragma unroll
        for (int s = 0; s < 4; s++) {
            float2 f0 = P2[s][t][r0 + g];
            float2 f1 = P2[s][t][r0 + g + 8];
#pragma unroll
            for (int nt = 0; nt < 8; nt++) {
                float2 bf = V2[s][t][nt * 8 + g];
                mma1x2(oacc[nt], f0, f1, bf);
            }
        }
    }

    // ---- epilogue ----
    float inv0 = 1.f / l0, inv1 = 1.f / l1;
    int rg = b2 * SS + q0 + r0 + g;
#pragma unroll
    for (int nt = 0; nt < 8; nt++) {
        int col = h * HD + nt * 8 + 2 * t;
        *(float2*)&zc[(size_t)rg * EE + col] =
            make_float2(oacc[nt][0] * inv0, oacc[nt][1] * inv0);
        *(float2*)&zc[(size_t)(rg + 8) * EE + col] =
            make_float2(oacc[nt][2] * inv1, oacc[nt][3] * inv1);
    }
    if (t == 0) {
        gm[base + q0 + r0 + g] = m0;
        gl[base + q0 + r0 + g] = l0;
        gm[base + q0 + r0 + g + 8] = m1;
        gl[base + q0 + r0 + g + 8] = l1;
    }
}

// =============================================================================
// attn zero-fill: strictly-upper 64x64 tiles (input-independent; runs early).
// =============================================================================
__global__ __launch_bounds__(256) void attn_zero(float* __restrict__ out)
{
    int qb = blockIdx.x >> 5, kb = blockIdx.x & 31;
    if (kb <= qb) return;
    int h = blockIdx.y, b2 = blockIdx.z;
    size_t obase = (size_t)(b2 * HH + h) * SS * SS;
    int q0 = qb * 64, k0 = kb * 64;
    float4 z = make_float4(0.f, 0.f, 0.f, 0.f);
    int tid = threadIdx.x;
#pragma unroll
    for (int l = 0; l < 4; l++) {
        int idx = l * 256 + tid;
        int row = idx >> 4, c4 = idx & 15;
        *(float4*)&out[obase + (size_t)(q0 + row) * SS + k0 + c4 * 4] = z;
    }
}

// =============================================================================
// attn normalize: lower-triangle 64x64 tiles only (triangular grid, 528).
// =============================================================================
__global__ __launch_bounds__(256) void attn_norm(const float* __restrict__ gm,
                                                 const float* __restrict__ gl,
                                                 float* __restrict__ attn)
{
    int bx = blockIdx.x;
    int qb = (int)floorf((sqrtf(8.f * bx + 1.f) - 1.f) * 0.5f);
    while ((qb + 1) * (qb + 2) / 2 <= bx) qb++;
    while (qb * (qb + 1) / 2 > bx) qb--;
    int kb = bx - qb * (qb + 1) / 2;

    int h = blockIdx.y, b2 = blockIdx.z;
    size_t obase = (size_t)(b2 * HH + h) * SS * SS;
    int q0 = qb * 64, k0 = kb * 64;
    int tid = threadIdx.x;

    __shared__ float ms[64], il[64];
    int base = (b2 * HH + h) * SS;
    if (tid < 64) {
        ms[tid] = gm[base + q0 + tid];
        il[tid] = 1.f / gl[base + q0 + tid];
    }
    __syncthreads();

#pragma unroll
    for (int l = 0; l < 4; l++) {
        int idx = l * 256 + tid;
        int row = idx >> 4, c4 = idx & 15;
        int grow = q0 + row;
        int gcol = k0 + c4 * 4;
        size_t off = obase + (size_t)grow * SS + gcol;
        float4 lg = *(const float4*)&attn[off];
        float mm = ms[row], ss = il[row];
        float4 p;
        p.x = (gcol     > grow) ? 0.f : __expf(lg.x - mm) * ss;
        p.y = (gcol + 1 > grow) ? 0.f : __expf(lg.y - mm) * ss;
        p.z = (gcol + 2 > grow) ? 0.f : __expf(lg.z - mm) * ss;
        p.w = (gcol + 3 > grow) ? 0.f : __expf(lg.w - mm) * ss;
        *(float4*)&attn[off] = p;
    }
}

// =============================================================================
// Host launcher — fork/join streams.
// =============================================================================
static cudaStream_t s_v = 0, s_n = 0;
static cudaEvent_t  e_root = 0, e_v = 0, e_attn = 0, e_n = 0;

extern "C" void kernel_launch(void* const* d_in, const int* in_sizes, int n_in,
                              void* d_out, int out_size)
{
    const float* q  = (const float*)d_in[0];
    const float* k  = (const float*)d_in[1];
    const float* v  = (const float*)d_in[2];
    const float* Wq = (const float*)d_in[4];
    const float* bq = (const float*)d_in[5];
    const float* Wk = (const float*)d_in[6];
    const float* bk = (const float*)d_in[7];
    const float* Wv = (const float*)d_in[8];
    const float* bv = (const float*)d_in[9];
    const float* Wz = (const float*)d_in[10];
    const float* bz = (const float*)d_in[11];
    float* out = (float*)d_out;

    if (!s_v) {
        cudaStreamCreateWithFlags(&s_v, cudaStreamNonBlocking);
        cudaStreamCreateWithFlags(&s_n, cudaStreamNonBlocking);
        cudaEventCreateWithFlags(&e_root, cudaEventDisableTiming);
        cudaEventCreateWithFlags(&e_v,    cudaEventDisableTiming);
        cudaEventCreateWithFlags(&e_attn, cudaEventDisableTiming);
        cudaEventCreateWithFlags(&e_n,    cudaEventDisableTiming);
    }

    float *proj, *zc, *gm, *gl, *vh;
    float4 *qsp, *ksp;
    cudaGetSymbolAddress((void**)&proj, g_proj);
    cudaGetSymbolAddress((void**)&qsp,  g_qsp);
    cudaGetSymbolAddress((void**)&ksp,  g_ksp);
    cudaGetSymbolAddress((void**)&vh,   g_vh);
    cudaGetSymbolAddress((void**)&zc,   g_zc);
    cudaGetSymbolAddress((void**)&gm,   g_m);
    cudaGetSymbolAddress((void**)&gl,   g_l);

    int need_attn = ((long long)out_size >= (long long)PROJ_ELEMS + (long long)ATTN_ELEMS);
    float* pattn = need_attn ? (out + PROJ_ELEMS) : (float*)0;

    size_t smG = (size_t)(4 * BUFSZ) * sizeof(float4);
    cudaFuncSetAttribute(gemm_3x, cudaFuncAttributeMaxDynamicSharedMemorySize, (int)smG);
    size_t smA = (size_t)(Q_SZ4 + K_SZ4) * sizeof(float4)
               + (size_t)(V_SZ2 + P_SZ2) * sizeof(float2);   // 68,608 B -> 3 CTAs/SM
    cudaFuncSetAttribute(attn_mma, cudaFuncAttributeMaxDynamicSharedMemorySize, (int)smA);

    // ---- fork: zero-fill (s_n) + v projection (s_v) concurrent with q,k proj ----
    cudaEventRecord(e_root, 0);
    cudaStreamWaitEvent(s_v, e_root, 0);
    cudaStreamWaitEvent(s_n, e_root, 0);

    if (need_attn)
        attn_zero<<<dim3(32 * 32, HH, BB), 256, 0, s_n>>>(pattn);

    GemmBatch pb;
    pb.A[0] = q;  pb.A[1] = k;
    pb.B[0] = Wq; pb.B[1] = Wk;
    pb.bias[0] = bq; pb.bias[1] = bk;
    pb.C[0] = proj;
    pb.C[1] = proj + (size_t)PROJ_ELEMS;
    gemm_3x<<<dim3(EE / 128, ROWS / 128, 2), 256, smG>>>(pb, ROWS, EE, EE);

    gemm_1x<<<dim3(EE / 128, ROWS / 128), 256, 0, s_v>>>(v, Wv, bv,
        proj + 2 * (size_t)PROJ_ELEMS, ROWS, EE, EE);
    cudaEventRecord(e_v, s_v);
    cudaStreamWaitEvent(0, e_v, 0);

    // ---- gather + pre-split + attention (main stream) ----
    gather_norm3<<<dim3(NHROWS / 8, 3), 256>>>(proj, qsp, ksp, vh);

    attn_mma<<<dim3(SS / 64, HH, BB), 128, smA>>>(
        qsp, ksp, vh, zc, gm, gl, pattn);

    // ---- fork: lower-triangle normalize concurrent with final GEMM ----
    cudaEventRecord(e_attn, 0);
    cudaStreamWaitEvent(s_n, e_attn, 0);

    if (need_attn)
        attn_norm<<<dim3(528, HH, BB), 256, 0, s_n>>>(gm, gl, pattn);

    gemm_1x<<<dim3(EE / 128, ROWS / 128), 256>>>(zc, Wz, bz, out, ROWS, EE, EE);

    cudaEventRecord(e_n, s_n);
    cudaStreamWaitEvent(0, e_n, 0);
}

// round 14
// speedup vs baseline: 1.1558x; 1.1558x over previous
#include <cuda_runtime.h>
#include <math.h>
#include <stdint.h>

// ---------------- problem constants ----------------
#define BB 2
#define SS 2048
#define EE 1024
#define HH 16
#define HD 64
#define ROWS (BB*SS)           // 4096
#define NHROWS (BB*HH*SS)      // 65536
#define PROJ_ELEMS (ROWS*EE)   // 4194304
#define ATTN_ELEMS (BB*HH*SS*SS) // 134217728

// ---------------- scratch ----------------
__device__ float g_proj[3][PROJ_ELEMS];
__device__ float g_heads[3][PROJ_ELEMS];
__device__ float g_zc[PROJ_ELEMS];
__device__ float g_m[NHROWS];
__device__ float g_l[NHROWS];

// ---------------- tf32 helpers ----------------
__device__ __forceinline__ float2 tf32split(float x) {
    uint32_t hi;
    asm("cvt.rna.tf32.f32 %0, %1;" : "=r"(hi) : "f"(x));
    float h = __uint_as_float(hi);
    uint32_t lo;
    asm("cvt.rna.tf32.f32 %0, %1;" : "=r"(lo) : "f"(x - h));
    return make_float2(h, __uint_as_float(lo));
}

__device__ __forceinline__ float tf32hi(float x) {
    uint32_t hi;
    asm("cvt.rna.tf32.f32 %0, %1;" : "=r"(hi) : "f"(x));
    return __uint_as_float(hi);
}

__device__ __forceinline__ void mma8(float c[4],
                                     uint32_t a0, uint32_t a1, uint32_t a2, uint32_t a3,
                                     uint32_t b0, uint32_t b1) {
    asm volatile(
        "mma.sync.aligned.m16n8k8.row.col.f32.tf32.tf32.f32 "
        "{%0,%1,%2,%3}, {%4,%5,%6,%7}, {%8,%9}, {%0,%1,%2,%3};\n"
        : "+f"(c[0]), "+f"(c[1]), "+f"(c[2]), "+f"(c[3])
        : "r"(a0), "r"(a1), "r"(a2), "r"(a3), "r"(b0), "r"(b1));
}

#define F2U(x) __float_as_uint(x)

// 3xTF32 (hi*hi + hi*lo + lo*hi), fp32 accumulate. f = {hi_a, lo_a, hi_b, lo_b}
__device__ __forceinline__ void mma3x4(float c[4],
                                       const float4 f0, const float4 f1,
                                       const float4 bf) {
    mma8(c, F2U(f0.x), F2U(f1.x), F2U(f0.z), F2U(f1.z), F2U(bf.x), F2U(bf.z));
    mma8(c, F2U(f0.x), F2U(f1.x), F2U(f0.z), F2U(f1.z), F2U(bf.y), F2U(bf.w));
    mma8(c, F2U(f0.y), F2U(f1.y), F2U(f0.w), F2U(f1.w), F2U(bf.x), F2U(bf.z));
}

// 1xTF32 on float2 hi-only fragments: f = {hi(k=t), hi(k=t+4)}
__device__ __forceinline__ void mma1x2(float c[4],
                                       const float2 f0, const float2 f1,
                                       const float2 bf) {
    mma8(c, F2U(f0.x), F2U(f1.x), F2U(f0.y), F2U(f1.y), F2U(bf.x), F2U(bf.y));
}

__device__ __forceinline__ float4 packsplit(float v0, float v1) {
    float2 h0 = tf32split(v0);
    float2 h1 = tf32split(v1);
    return make_float4(h0.x, h0.y, h1.x, h1.y);
}

// =============================================================================
// Batched 128x128x16 3xTF32 GEMM (q,k projections), double-buffered (R8 config).
// =============================================================================
struct GemmBatch {
    const float* A[2];
    const float* B[2];
    const float* bias[2];
    float* C[2];
};

#define BUFSZ  (2*4*130)   // one float4 buffer: [2 khalf][4 t][130]

__global__ __launch_bounds__(256) void gemm_3x(GemmBatch args, int M, int N, int K)
{
    extern __shared__ float4 smemg[];
    float4 (*Apk)[2][4][130] = (float4(*)[2][4][130])smemg;
    float4 (*Bpk)[2][4][130] = (float4(*)[2][4][130])(smemg + 2 * BUFSZ);

    const float* A    = args.A[blockIdx.z];
    const float* B    = args.B[blockIdx.z];
    const float* bias = args.bias[blockIdx.z];
    float*       C    = args.C[blockIdx.z];

    int tid = threadIdx.x;
    int wid = tid >> 5, lane = tid & 31;
    int g = lane >> 2, t = lane & 3;
    int wm = wid >> 2, wn = wid & 3;
    int m0 = blockIdx.y * 128, n0 = blockIdx.x * 128;

    int ma = tid & 127, ha = tid >> 7;
    int nq = tid & 31,  kr = tid >> 5;
    int bs = kr >> 2,   bt = kr & 3;

    float acc[4][4][4];
#pragma unroll
    for (int mt = 0; mt < 4; mt++)
#pragma unroll
        for (int nt = 0; nt < 4; nt++)
#pragma unroll
            for (int c = 0; c < 4; c++) acc[mt][nt][c] = 0.f;

    const int NC = K / 16;
    float4 pa0, pa1, pb0, pb1;
    {
        const float* pA = A + (size_t)(m0 + ma) * K + ha * 8;
        pa0 = *(const float4*)pA;
        pa1 = *(const float4*)(pA + 4);
        const float* pB = B + (size_t)(bs * 8 + bt) * N + n0 + nq * 4;
        pb0 = *(const float4*)pB;
        pb1 = *(const float4*)(pB + 4 * (size_t)N);
    }

    for (int c = 0; c < NC; c++) {
        int buf = c & 1;
        {
            float va[8] = {pa0.x, pa0.y, pa0.z, pa0.w, pa1.x, pa1.y, pa1.z, pa1.w};
            float vb0[4] = {pb0.x, pb0.y, pb0.z, pb0.w};
            float vb1[4] = {pb1.x, pb1.y, pb1.z, pb1.w};
#pragma unroll
            for (int tt = 0; tt < 4; tt++)
                Apk[buf][ha][tt][ma] = packsplit(va[tt], va[tt + 4]);
#pragma unroll
            for (int j = 0; j < 4; j++)
                Bpk[buf][bs][bt][nq * 4 + j] = packsplit(vb0[j], vb1[j]);
        }
        if (c + 1 < NC) {
            int k0 = (c + 1) * 16;
            const float* pA = A + (size_t)(m0 + ma) * K + k0 + ha * 8;
            pa0 = *(const float4*)pA;
            pa1 = *(const float4*)(pA + 4);
            const float* pB = B + (size_t)(k0 + bs * 8 + bt) * N + n0 + nq * 4;
            pb0 = *(const float4*)pB;
            pb1 = *(const float4*)(pB + 4 * (size_t)N);
        }
        __syncthreads();
#pragma unroll
        for (int s = 0; s < 2; s++) {
            float4 af0[4], af1[4];
#pragma unroll
            for (int mt = 0; mt < 4; mt++) {
                int rb = wm * 64 + mt * 16;
                af0[mt] = Apk[buf][s][t][rb + g];
                af1[mt] = Apk[buf][s][t][rb + g + 8];
            }
#pragma unroll
            for (int nt = 0; nt < 4; nt++) {
                float4 bf = Bpk[buf][s][t][wn * 32 + nt * 8 + g];
#pragma unroll
                for (int mt = 0; mt < 4; mt++)
                    mma3x4(acc[mt][nt], af0[mt], af1[mt], bf);
            }
        }
    }

#pragma unroll
    for (int mt = 0; mt < 4; mt++) {
        int r = m0 + wm * 64 + mt * 16 + g;
#pragma unroll
        for (int nt = 0; nt < 4; nt++) {
            int cc = n0 + wn * 32 + nt * 8 + 2 * t;
            float bb0 = bias[cc], bb1 = bias[cc + 1];
            *(float2*)&C[(size_t)r * N + cc] =
                make_float2(acc[mt][nt][0] + bb0, acc[mt][nt][1] + bb1);
            *(float2*)&C[(size_t)(r + 8) * N + cc] =
                make_float2(acc[mt][nt][2] + bb0, acc[mt][nt][3] + bb1);
        }
    }
}

// =============================================================================
// 128x128x16 1xTF32 GEMM, float2 hi-only smem, 2 CTAs/SM.
// =============================================================================
__global__ __launch_bounds__(256, 2) void gemm_1x(const float* __restrict__ A,
                                                  const float* __restrict__ B,
                                                  const float* __restrict__ bias,
                                                  float* __restrict__ C,
                                                  int M, int N, int K)
{
    __shared__ float2 A2[2][2][4][132];
    __shared__ float2 B2[2][2][4][132];

    int tid = threadIdx.x;
    int wid = tid >> 5, lane = tid & 31;
    int g = lane >> 2, t = lane & 3;
    int wm = wid >> 2, wn = wid & 3;
    int m0 = blockIdx.y * 128, n0 = blockIdx.x * 128;

    int ma = tid & 127, ha = tid >> 7;
    int nq = tid & 31,  kr = tid >> 5;
    int bs = kr >> 2,   bt = kr & 3;

    float acc[4][4][4];
#pragma unroll
    for (int mt = 0; mt < 4; mt++)
#pragma unroll
        for (int nt = 0; nt < 4; nt++)
#pragma unroll
            for (int c = 0; c < 4; c++) acc[mt][nt][c] = 0.f;

    const int NC = K / 16;
    float4 pa0, pa1;
    float vb0[4], vb1[4];
    {
        const float* pA = A + (size_t)(m0 + ma) * K + ha * 8;
        pa0 = *(const float4*)pA;
        pa1 = *(const float4*)(pA + 4);
        const float* pB0 = B + (size_t)(bs * 8 + bt) * N + n0 + nq;
        const float* pB1 = pB0 + 4 * (size_t)N;
#pragma unroll
        for (int j = 0; j < 4; j++) { vb0[j] = pB0[j * 32]; vb1[j] = pB1[j * 32]; }
    }

    for (int c = 0; c < NC; c++) {
        int buf = c & 1;
        {
            float va[8] = {pa0.x, pa0.y, pa0.z, pa0.w, pa1.x, pa1.y, pa1.z, pa1.w};
#pragma unroll
            for (int tt = 0; tt < 4; tt++)
                A2[buf][ha][tt][ma] = make_float2(tf32hi(va[tt]), tf32hi(va[tt + 4]));
#pragma unroll
            for (int j = 0; j < 4; j++)
                B2[buf][bs][bt][j * 32 + nq] = make_float2(tf32hi(vb0[j]), tf32hi(vb1[j]));
        }
        if (c + 1 < NC) {
            int k0 = (c + 1) * 16;
            const float* pA = A + (size_t)(m0 + ma) * K + k0 + ha * 8;
            pa0 = *(const float4*)pA;
            pa1 = *(const float4*)(pA + 4);
            const float* pB0 = B + (size_t)(k0 + bs * 8 + bt) * N + n0 + nq;
            const float* pB1 = pB0 + 4 * (size_t)N;
#pragma unroll
            for (int j = 0; j < 4; j++) { vb0[j] = pB0[j * 32]; vb1[j] = pB1[j * 32]; }
        }
        __syncthreads();
#pragma unroll
        for (int s = 0; s < 2; s++) {
            float2 af0[4], af1[4];
#pragma unroll
            for (int mt = 0; mt < 4; mt++) {
                int rb = wm * 64 + mt * 16;
                af0[mt] = A2[buf][s][t][rb + g];
                af1[mt] = A2[buf][s][t][rb + g + 8];
            }
#pragma unroll
            for (int nt = 0; nt < 4; nt++) {
                float2 bf = B2[buf][s][t][wn * 32 + nt * 8 + g];
#pragma unroll
                for (int mt = 0; mt < 4; mt++)
                    mma1x2(acc[mt][nt], af0[mt], af1[mt], bf);
            }
        }
    }

#pragma unroll
    for (int mt = 0; mt < 4; mt++) {
        int r = m0 + wm * 64 + mt * 16 + g;
#pragma unroll
        for (int nt = 0; nt < 4; nt++) {
            int cc = n0 + wn * 32 + nt * 8 + 2 * t;
            float bb0 = bias[cc], bb1 = bias[cc + 1];
            *(float2*)&C[(size_t)r * N + cc] =
                make_float2(acc[mt][nt][0] + bb0, acc[mt][nt][1] + bb1);
            *(float2*)&C[(size_t)(r + 8) * N + cc] =
                make_float2(acc[mt][nt][2] + bb0, acc[mt][nt][3] + bb1);
        }
    }
}

// =============================================================================
// Gather + optional L2-normalize. which = which_off + blockIdx.y
// (0=q norm, 1=k norm, 2=v no-norm). Split launches let v-gather hide
// under the q/k projection on a side stream.
// =============================================================================
__global__ __launch_bounds__(256) void gather_norm3(const float* __restrict__ proj_base,
                                                    float* __restrict__ heads_base,
                                                    int which_off)
{
    int which = which_off + blockIdx.y;
    const float* proj = proj_base + (size_t)which * PROJ_ELEMS;
    float* outp = heads_base + (size_t)which * PROJ_ELEMS;
    int do_norm = (which < 2);

    int w = blockIdx.x * 8 + (threadIdx.x >> 5);
    int lane = threadIdx.x & 31;
    int b2 = w >> 15;
    int h  = (w >> 11) & 15;
    int s2 = w & 2047;
    int e = b2 * 512 + h * 32 + (s2 >> 6);
    int s = ((s2 & 63) << 5) + lane;
    float v0 = proj[(size_t)s * EE + e];
    float v1 = proj[(size_t)(SS + s) * EE + e];
    float rn = 1.0f;
    if (do_norm) {
        float ssq = v0 * v0 + v1 * v1;
#pragma unroll
        for (int o = 16; o; o >>= 1) ssq += __shfl_xor_sync(0xffffffffu, ssq, o);
        rn = rsqrtf(ssq);
    }
    ((float2*)outp)[(size_t)w * 32 + lane] = make_float2(v0 * rn, v1 * rn);
}

// =============================================================================
// mma flash attention, BQ=64 / BK=32, 128 threads (4 warps x 16 q-rows),
// 3 CTAs/SM. QK^T at 3xTF32; P@V at 1xTF32 float2 hi-only smem.
// LPT block ordering. Streams raw logits to pattn.  (R8 kernel, unchanged.)
// =============================================================================
#define Q_SZ4 (8*4*66)   // float4s
#define K_SZ4 (8*4*34)   // float4s
#define V_SZ2 (4*4*68)   // float2s
#define P_SZ2 (4*4*68)   // float2s

__global__ __launch_bounds__(128, 3) void attn_mma(const float* __restrict__ qn,
                                                   const float* __restrict__ kn,
                                                   const float* __restrict__ vh,
                                                   float* __restrict__ zc,
                                                   float* __restrict__ gm,
                                                   float* __restrict__ gl,
                                                   float* __restrict__ pattn)
{
    extern __shared__ float4 sm4[];
    float4 (*Qpk)[4][66] = (float4(*)[4][66])sm4;                      // [8][4][66] f4
    float4 (*Kpk)[4][34] = (float4(*)[4][34])(sm4 + Q_SZ4);            // [8][4][34] f4
    float2 (*V2)[4][68]  = (float2(*)[4][68])(sm4 + Q_SZ4 + K_SZ4);    // [4][4][68] f2
    float2 (*P2)[4][68]  = (float2(*)[4][68])((float2*)(sm4 + Q_SZ4 + K_SZ4) + V_SZ2);

    int tid = threadIdx.x;
    int w = tid >> 5, lane = tid & 31;
    int g = lane >> 2, t = lane & 3;
    int qb = (gridDim.x - 1) - blockIdx.x;   // LPT: heavy blocks first
    int h = blockIdx.y, b2 = blockIdx.z;
    int base = (b2 * HH + h) * SS;
    size_t obase = (size_t)(b2 * HH + h) * SS * SS;
    int q0 = qb * 64;
    int r0 = w * 16;

    // ---- stage Q (hi+lo float4) ----
    {
        int m = tid >> 1, hs = tid & 1;
        const float4* src = (const float4*)(qn + (size_t)(base + q0 + m) * HD + hs * 32);
        float4 v[8];
#pragma unroll
        for (int j = 0; j < 8; j++) v[j] = src[j];
        const float* vf = (const float*)v;
#pragma unroll
        for (int sp = 0; sp < 4; sp++)
#pragma unroll
            for (int tt = 0; tt < 4; tt++)
                Qpk[hs * 4 + sp][tt][m] = packsplit(vf[8 * sp + tt], vf[8 * sp + tt + 4]);
    }

    float oacc[8][4];
#pragma unroll
    for (int nt = 0; nt < 8; nt++)
#pragma unroll
        for (int c = 0; c < 4; c++) oacc[nt][c] = 0.f;
    float m0 = -1e30f, m1 = -1e30f, l0 = 0.f, l1 = 0.f;

    int row0 = q0 + r0 + g, row1 = row0 + 8;
    int nkb = 2 * (qb + 1);

    for (int kb = 0; kb < nkb; kb++) {
        int k0 = kb * 32;
        __syncthreads();
        // ---- stage K tile (hi+lo) ----
        {
            int n = tid >> 2, qk = tid & 3;
            const float4* src = (const float4*)(kn + (size_t)(base + k0 + n) * HD + qk * 16);
            float4 v[4];
#pragma unroll
            for (int j = 0; j < 4; j++) v[j] = src[j];
            const float* vf = (const float*)v;
#pragma unroll
            for (int sp = 0; sp < 2; sp++)
#pragma unroll
                for (int tt = 0; tt < 4; tt++)
                    Kpk[qk * 2 + sp][tt][n] = packsplit(vf[8 * sp + tt], vf[8 * sp + tt + 4]);
        }
        // ---- stage V tile (hi-only float2) ----
        {
            int n4 = tid & 15;
            int comb = tid >> 4;
            int s = comb >> 1, tb = (comb & 1) * 2;
#pragma unroll
            for (int dt = 0; dt < 2; dt++) {
                int tt = tb + dt;
                const float* p = vh + (size_t)(base + k0 + 8 * s + tt) * HD + n4 * 4;
                float4 x0 = *(const float4*)p;
                float4 x1 = *(const float4*)(p + 4 * HD);
                const float* f0 = (const float*)&x0;
                const float* f1 = (const float*)&x1;
#pragma unroll
                for (int j = 0; j < 4; j++)
                    V2[s][tt][n4 * 4 + j] = make_float2(tf32hi(f0[j]), tf32hi(f1[j]));
            }
        }
        __syncthreads();

        if (k0 > q0 + r0 + 15) continue;

        // ---- S = Q @ K^T (3xTF32) ----
        float sacc[4][4];
#pragma unroll
        for (int nt = 0; nt < 4; nt++)
#pragma unroll
            for (int c = 0; c < 4; c++) sacc[nt][c] = 0.f;
#pragma unroll
        for (int ks = 0; ks < 8; ks++) {
            float4 f0 = Qpk[ks][t][r0 + g];
            float4 f1 = Qpk[ks][t][r0 + g + 8];
#pragma unroll
            for (int nt = 0; nt < 4; nt++) {
                float4 bf = Kpk[ks][t][nt * 8 + g];
                mma3x4(sacc[nt], f0, f1, bf);
            }
        }

        // ---- scale + mask ----
        bool nm = (k0 + 31 > q0 + r0);
        float sv[4][4];
        float mx0 = -1e30f, mx1 = -1e30f;
#pragma unroll
        for (int nt = 0; nt < 4; nt++) {
            int cb = k0 + nt * 8 + 2 * t;
            float s0 = sacc[nt][0] * 1000.f;
            float s1 = sacc[nt][1] * 1000.f;
            float s2 = sacc[nt][2] * 1000.f;
            float s3 = sacc[nt][3] * 1000.f;
            if (nm) {
                if (cb > row0) s0 = -1e30f;
                if (cb + 1 > row0) s1 = -1e30f;
                if (cb > row1) s2 = -1e30f;
                if (cb + 1 > row1) s3 = -1e30f;
            }
            sv[nt][0] = s0; sv[nt][1] = s1; sv[nt][2] = s2; sv[nt][3] = s3;
            mx0 = fmaxf(mx0, fmaxf(s0, s1));
            mx1 = fmaxf(mx1, fmaxf(s2, s3));
        }

        // ---- stream logits to attn buffer ----
        if (pattn) {
#pragma unroll
            for (int nt = 0; nt < 4; nt++) {
                int jg = k0 + nt * 8 + 2 * t;
                *(float2*)&pattn[obase + (size_t)row0 * SS + jg] = make_float2(sv[nt][0], sv[nt][1]);
                *(float2*)&pattn[obase + (size_t)row1 * SS + jg] = make_float2(sv[nt][2], sv[nt][3]);
            }
        }

        // ---- online softmax ----
        mx0 = fmaxf(mx0, __shfl_xor_sync(0xffffffffu, mx0, 1));
        mx0 = fmaxf(mx0, __shfl_xor_sync(0xffffffffu, mx0, 2));
        mx1 = fmaxf(mx1, __shfl_xor_sync(0xffffffffu, mx1, 1));
        mx1 = fmaxf(mx1, __shfl_xor_sync(0xffffffffu, mx1, 2));
        float mn0 = fmaxf(m0, mx0), mn1 = fmaxf(m1, mx1);
        float sc0 = __expf(m0 - mn0), sc1 = __expf(m1 - mn1);
        m0 = mn0; m1 = mn1;
        float rs0 = 0.f, rs1 = 0.f;
        int tpA = (2 * t) & 3, tpB = (2 * t + 1) & 3;
        int slot = (t >= 2);
#pragma unroll
        for (int nt = 0; nt < 4; nt++) {
            float p0 = __expf(sv[nt][0] - mn0);
            float p1 = __expf(sv[nt][1] - mn0);
            float p2 = __expf(sv[nt][2] - mn1);
            float p3 = __expf(sv[nt][3] - mn1);
            rs0 += p0 + p1;
            rs1 += p2 + p3;
            ((float*)&P2[nt][tpA][r0 + g])[slot]     = tf32hi(p0);
            ((float*)&P2[nt][tpB][r0 + g])[slot]     = tf32hi(p1);
            ((float*)&P2[nt][tpA][r0 + g + 8])[slot] = tf32hi(p2);
            ((float*)&P2[nt][tpB][r0 + g + 8])[slot] = tf32hi(p3);
        }
        rs0 += __shfl_xor_sync(0xffffffffu, rs0, 1);
        rs0 += __shfl_xor_sync(0xffffffffu, rs0, 2);
        rs1 += __shfl_xor_sync(0xffffffffu, rs1, 1);
        rs1 += __shfl_xor_sync(0xffffffffu, rs1, 2);
        l0 = l0 * sc0 + rs0;
        l1 = l1 * sc1 + rs1;
#pragma unroll
        for (int nt = 0; nt < 8; nt++) {
            oacc[nt][0] *= sc0; oacc[nt][1] *= sc0;
            oacc[nt][2] *= sc1; oacc[nt][3] *= sc1;
        }
        __syncwarp();

        // ---- O += P @ V (1xTF32, float2 fragments) ----
#pragma unroll
        for (int s = 0; s < 4; s++) {
            float2 f0 = P2[s][t][r0 + g];
            float2 f1 = P2[s][t][r0 + g + 8];
#pragma unroll
            for (int nt = 0; nt < 8; nt++) {
                float2 bf = V2[s][t][nt * 8 + g];
                mma1x2(oacc[nt], f0, f1, bf);
            }
        }
    }

    // ---- epilogue ----
    float inv0 = 1.f / l0, inv1 = 1.f / l1;
    int rg = b2 * SS + q0 + r0 + g;
#pragma unroll
    for (int nt = 0; nt < 8; nt++) {
        int col = h * HD + nt * 8 + 2 * t;
        *(float2*)&zc[(size_t)rg * EE + col] =
            make_float2(oacc[nt][0] * inv0, oacc[nt][1] * inv0);
        *(float2*)&zc[(size_t)(rg + 8) * EE + col] =
            make_float2(oacc[nt][2] * inv1, oacc[nt][3] * inv1);
    }
    if (t == 0) {
        gm[base + q0 + r0 + g] = m0;
        gl[base + q0 + r0 + g] = l0;
        gm[base + q0 + r0 + g + 8] = m1;
        gl[base + q0 + r0 + g + 8] = l1;
    }
}

// =============================================================================
// attn normalize: in-place exp(logit - m)/l on lower tiles; zero upper tiles.
// (R8 combined version — overlapped with final GEMM.)
// =============================================================================
__global__ __launch_bounds__(256) void attn_norm(const float* __restrict__ gm,
                                                 const float* __restrict__ gl,
                                                 float* __restrict__ attn)
{
    int qb = blockIdx.x >> 5, kb = blockIdx.x & 31;
    int h = blockIdx.y, b2 = blockIdx.z;
    size_t obase = (size_t)(b2 * HH + h) * SS * SS;
    int q0 = qb * 64, k0 = kb * 64;
    int tid = threadIdx.x;

    if (kb > qb) {
        float4 z = make_float4(0.f, 0.f, 0.f, 0.f);
#pragma unroll
        for (int l = 0; l < 4; l++) {
            int idx = l * 256 + tid;
            int row = idx >> 4, c4 = idx & 15;
            *(float4*)&attn[obase + (size_t)(q0 + row) * SS + k0 + c4 * 4] = z;
        }
        return;
    }

    __shared__ float ms[64], il[64];
    int base = (b2 * HH + h) * SS;
    if (tid < 64) {
        ms[tid] = gm[base + q0 + tid];
        il[tid] = 1.f / gl[base + q0 + tid];
    }
    __syncthreads();

#pragma unroll
    for (int l = 0; l < 4; l++) {
        int idx = l * 256 + tid;
        int row = idx >> 4, c4 = idx & 15;
        int grow = q0 + row;
        int gcol = k0 + c4 * 4;
        size_t off = obase + (size_t)grow * SS + gcol;
        float4 lg = *(const float4*)&attn[off];
        float mm = ms[row], ss = il[row];
        float4 p;
        p.x = (gcol     > grow) ? 0.f : __expf(lg.x - mm) * ss;
        p.y = (gcol + 1 > grow) ? 0.f : __expf(lg.y - mm) * ss;
        p.z = (gcol + 2 > grow) ? 0.f : __expf(lg.z - mm) * ss;
        p.w = (gcol + 3 > grow) ? 0.f : __expf(lg.w - mm) * ss;
        *(float4*)&attn[off] = p;
    }
}

// =============================================================================
// Host launcher — fork/join streams (R8 structure + hidden v-gather).
// =============================================================================
static cudaStream_t s_v = 0, s_n = 0;
static cudaEvent_t  e_root = 0, e_v = 0, e_attn = 0, e_n = 0;

extern "C" void kernel_launch(void* const* d_in, const int* in_sizes, int n_in,
                              void* d_out, int out_size)
{
    const float* q  = (const float*)d_in[0];
    const float* k  = (const float*)d_in[1];
    const float* v  = (const float*)d_in[2];
    const float* Wq = (const float*)d_in[4];
    const float* bq = (const float*)d_in[5];
    const float* Wk = (const float*)d_in[6];
    const float* bk = (const float*)d_in[7];
    const float* Wv = (const float*)d_in[8];
    const float* bv = (const float*)d_in[9];
    const float* Wz = (const float*)d_in[10];
    const float* bz = (const float*)d_in[11];
    float* out = (float*)d_out;

    if (!s_v) {
        cudaStreamCreateWithFlags(&s_v, cudaStreamNonBlocking);
        cudaStreamCreateWithFlags(&s_n, cudaStreamNonBlocking);
        cudaEventCreateWithFlags(&e_root, cudaEventDisableTiming);
        cudaEventCreateWithFlags(&e_v,    cudaEventDisableTiming);
        cudaEventCreateWithFlags(&e_attn, cudaEventDisableTiming);
        cudaEventCreateWithFlags(&e_n,    cudaEventDisableTiming);
    }

    float *proj, *heads, *zc, *gm, *gl;
    cudaGetSymbolAddress((void**)&proj,  g_proj);
    cudaGetSymbolAddress((void**)&heads, g_heads);
    cudaGetSymbolAddress((void**)&zc,    g_zc);
    cudaGetSymbolAddress((void**)&gm,    g_m);
    cudaGetSymbolAddress((void**)&gl,    g_l);

    int need_attn = ((long long)out_size >= (long long)PROJ_ELEMS + (long long)ATTN_ELEMS);
    float* pattn = need_attn ? (out + PROJ_ELEMS) : (float*)0;

    size_t smG = (size_t)(4 * BUFSZ) * sizeof(float4);
    cudaFuncSetAttribute(gemm_3x, cudaFuncAttributeMaxDynamicSharedMemorySize, (int)smG);
    size_t smA = (size_t)(Q_SZ4 + K_SZ4) * sizeof(float4)
               + (size_t)(V_SZ2 + P_SZ2) * sizeof(float2);   // 68,608 B -> 3 CTAs/SM
    cudaFuncSetAttribute(attn_mma, cudaFuncAttributeMaxDynamicSharedMemorySize, (int)smA);

    // ---- fork: v projection + v-gather run concurrently with q,k projections ----
    cudaEventRecord(e_root, 0);
    cudaStreamWaitEvent(s_v, e_root, 0);

    GemmBatch pb;
    pb.A[0] = q;  pb.A[1] = k;
    pb.B[0] = Wq; pb.B[1] = Wk;
    pb.bias[0] = bq; pb.bias[1] = bk;
    pb.C[0] = proj;
    pb.C[1] = proj + (size_t)PROJ_ELEMS;
    gemm_3x<<<dim3(EE / 128, ROWS / 128, 2), 256, smG>>>(pb, ROWS, EE, EE);

    gemm_1x<<<dim3(EE / 128, ROWS / 128), 256, 0, s_v>>>(v, Wv, bv,
        proj + 2 * (size_t)PROJ_ELEMS, ROWS, EE, EE);
    gather_norm3<<<dim3(NHROWS / 8, 1), 256, 0, s_v>>>(proj, heads, 2);  // v-gather, hidden
    cudaEventRecord(e_v, s_v);
    cudaStreamWaitEvent(0, e_v, 0);

    // ---- q,k gather + attention (main stream) ----
    gather_norm3<<<dim3(NHROWS / 8, 2), 256>>>(proj, heads, 0);

    attn_mma<<<dim3(SS / 64, HH, BB), 128, smA>>>(
        heads, heads + (size_t)PROJ_ELEMS, heads + 2 * (size_t)PROJ_ELEMS,
        zc, gm, gl, pattn);

    // ---- fork: attn normalize concurrent with final GEMM ----
    cudaEventRecord(e_attn, 0);
    cudaStreamWaitEvent(s_n, e_attn, 0);

    if (need_attn)
        attn_norm<<<dim3(32 * 32, HH, BB), 256, 0, s_n>>>(gm, gl, pattn);

    gemm_1x<<<dim3(EE / 128, ROWS / 128), 256>>>(zc, Wz, bz, out, ROWS, EE, EE);

    cudaEventRecord(e_n, s_n);
    cudaStreamWaitEvent(0, e_n, 0);
}